// round 2
// baseline (speedup 1.0000x reference)
#include <cuda_runtime.h>
#include <cstddef>

// DotMatrix on GB300. out[b,i,j,t,c] = complex dot over m of A_i with the
// SO3-conjugated A_j, concatenated over ell in {0..3}, tau=32 per ell.
//
// Identity: sum_m A_i[m]*sign(m)*A_j[M-1-m] == sum_m (sign(m)*A_i[M-1-m])*A_j[m]
// (sign is parity-symmetric under the flip), so flip+sign folds into the
// register-resident i-side factor and the j-tile is copied to smem raw.
//
// R2: packed fp32x2 math over tau pairs (fma.rn.f32x2), transposed smem
// [jl][m][c][tau] (conflict-free, warp-broadcast LDS.64), ell-outer loop
// (28KB smem, <=56 A regs), STG.128 output stores, launch_bounds(128,5).

using ull = unsigned long long;

namespace cfg {
constexpr int kB = 2;
constexpr int kN = 256;
constexpr int kT = 32;       // taus per ell
constexpr int JT = 16;       // j-tile
constexpr int IT = 16;       // i-tile (ty 8 x KI 2)
constexpr int KI = 2;
constexpr int TY = 8;
constexpr int TP = 16;       // tau pairs
constexpr int NTHREADS = TP * TY;       // 128
constexpr int SH_ULL = JT * 7 * 2 * 16; // max over ells: 3584 ull = 28KB
}

__device__ __forceinline__ void fma2(ull& d, ull a, ull b) {
  asm("fma.rn.f32x2 %0, %1, %2, %0;" : "+l"(d) : "l"(a), "l"(b));
}
__device__ __forceinline__ ull f2u(float x, float y) {
  ull v; asm("mov.b64 %0, {%1, %2};" : "=l"(v) : "f"(x), "f"(y)); return v;
}
__device__ __forceinline__ float2 u2f(ull v) {
  float2 f; asm("mov.b64 {%0, %1}, %2;" : "=f"(f.x), "=f"(f.y) : "l"(v)); return f;
}

template <int ELL>
__device__ __forceinline__ void processEll(const float* __restrict__ rep,
                                           ull* __restrict__ shv,
                                           int b, int i0, int j0,
                                           int tp, int ty, int tid,
                                           float4* __restrict__ out) {
  using namespace cfg;
  constexpr int M = 2 * ELL + 1;

  // ---- copy B tile to transposed smem: floats laid out ((jl*M+m)*2+c)*32+tau
  {
    const float2* src = reinterpret_cast<const float2*>(rep) +
                        (size_t)(b * kN + j0) * (kT * M);
    float* shf = reinterpret_cast<float*>(shv);
    constexpr int CNT = JT * kT * M;      // complex elements; m fastest
#pragma unroll
    for (int k = 0; k < CNT / NTHREADS; ++k) {
      int idx = tid + k * NTHREADS;
      float2 v = src[idx];                // idx = (jl*32+tau)*M + m  (coalesced)
      int m = idx % M;
      int jt = idx / M;
      int tau = jt & 31;
      int jl = jt >> 5;
      int fo = (jl * M + m) * 64 + tau;
      shf[fo] = v.x;
      shf[fo + 32] = v.y;
    }
  }

  // ---- load A packed (flip+sign folded): KI i's, tau pair {2tp, 2tp+1}
  ull ar2[KI][M], ai2[KI][M];
#pragma unroll
  for (int ki = 0; ki < KI; ++ki) {
    int i = i0 + ty + ki * TY;
    const float2* ab = reinterpret_cast<const float2*>(rep) +
                       (size_t)(b * kN + i) * (kT * M);
#pragma unroll
    for (int m = 0; m < M; ++m) {
      float2 v0 = __ldg(&ab[(2 * tp) * M + (M - 1 - m)]);
      float2 v1 = __ldg(&ab[(2 * tp + 1) * M + (M - 1 - m)]);
      float s = ((m + ELL) & 1) ? -1.0f : 1.0f;
      ar2[ki][m] = f2u(s * v0.x, s * v1.x);
      ai2[ki][m] = f2u(s * v0.y, s * v1.y);
    }
  }
  __syncthreads();

  // per-ki output base (float4 units): row (b,i), col j0, channel ELL*32+2tp
  size_t obase[KI];
#pragma unroll
  for (int ki = 0; ki < KI; ++ki) {
    int i = i0 + ty + ki * TY;
    obase[ki] = ((size_t)(b * kN + i) * kN + j0) * 64 + ELL * 16 + tp;
  }

#pragma unroll 2
  for (int jl = 0; jl < JT; ++jl) {
    const ull* bp = shv + (size_t)jl * (M * 32) + tp;  // ull stride per (m,c): 16
    ull a1[KI], a2[KI], aci[KI];
#pragma unroll
    for (int ki = 0; ki < KI; ++ki) { a1[ki] = 0ull; a2[ki] = 0ull; aci[ki] = 0ull; }
#pragma unroll
    for (int m = 0; m < M; ++m) {
      ull bx2 = bp[(2 * m) * 16];      // (bx_t0, bx_t1) broadcast across ty
      ull by2 = bp[(2 * m + 1) * 16];  // (by_t0, by_t1)
#pragma unroll
      for (int ki = 0; ki < KI; ++ki) {
        fma2(a1[ki],  ar2[ki][m], bx2);
        fma2(a2[ki],  ai2[ki][m], by2);
        fma2(aci[ki], ar2[ki][m], by2);
        fma2(aci[ki], ai2[ki][m], bx2);
      }
    }
#pragma unroll
    for (int ki = 0; ki < KI; ++ki) {
      float2 r1 = u2f(a1[ki]);
      float2 r2 = u2f(a2[ki]);
      float2 im = u2f(aci[ki]);
      // layout per (i,j): [t][c] -> tau0:(re,im), tau1:(re,im) = one float4
      out[obase[ki] + (size_t)jl * 64] =
          make_float4(r1.x - r2.x, im.x, r1.y - r2.y, im.y);
    }
  }
  __syncthreads();  // smem reused by next ell
}

__global__ void __launch_bounds__(cfg::NTHREADS, 5)
dotmat_kernel(const float* __restrict__ r0, const float* __restrict__ r1,
              const float* __restrict__ r2, const float* __restrict__ r3,
              float4* __restrict__ out) {
  using namespace cfg;
  __shared__ ull shv[SH_ULL];
  const int tp = threadIdx.x;   // tau pair
  const int ty = threadIdx.y;
  const int tid = ty * TP + tp;
  const int j0 = blockIdx.x * JT;
  const int i0 = blockIdx.y * IT;
  const int b  = blockIdx.z;

  processEll<0>(r0, shv, b, i0, j0, tp, ty, tid, out);
  processEll<1>(r1, shv, b, i0, j0, tp, ty, tid, out);
  processEll<2>(r2, shv, b, i0, j0, tp, ty, tid, out);
  processEll<3>(r3, shv, b, i0, j0, tp, ty, tid, out);
}

extern "C" void kernel_launch(void* const* d_in, const int* in_sizes, int n_in,
                              void* d_out, int out_size) {
  (void)in_sizes; (void)n_in; (void)out_size;
  dim3 grid(cfg::kN / cfg::JT, cfg::kN / cfg::IT, cfg::kB);
  dim3 block(cfg::TP, cfg::TY);
  dotmat_kernel<<<grid, block>>>(
      (const float*)d_in[0], (const float*)d_in[1],
      (const float*)d_in[2], (const float*)d_in[3],
      (float4*)d_out);
}

// round 3
// speedup vs baseline: 1.3084x; 1.3084x over previous
#include <cuda_runtime.h>
#include <cstddef>

// DotMatrix on GB300 (sm_103a).
// out[b,i,j,t,c] = complex dot over m of A_i with SO3-conjugated A_j,
// concatenated over ell in {0..3} (M = 2*ell+1), tau = 32 per ell.
//
// Identity 1 (fold): sum_m A_i[m]*sign(m)*A_j[M-1-m]
//                  == sum_m (sign(m)*A_i[M-1-m]) * A_j[m]
//   -> flip+sign lives in the register-resident i-side; j-tile copied raw.
// Identity 2 (symmetry): out[b,i,j,:] == out[b,j,i,:] for BOTH real and imag
//   components (substitute m -> M-1-m; sign is parity-symmetric).
//   -> compute only upper-triangular tile pairs, mirror-store the rest.
//   This halves FMA work; stores stay coalesced (tau is the lane dim).

namespace cfg {
constexpr int kN = 256;
constexpr int kT = 32;                    // taus per ell
constexpr int JT = 16;                    // j-tile
constexpr int IT = 16;                    // i-tile = TY * KI
constexpr int KI = 2;
constexpr int TY = 8;
constexpr int NT = 32 * TY;               // 256 threads
constexpr int NB = kN / JT;               // 16 tile-blocks per dim
constexpr int NPAIRS = NB * (NB + 1) / 2; // 136 upper-tri pairs
constexpr int SHF = JT * kT * 7 * 2;      // max B tile (ell=3): 7168 f = 28KB
}

template <int ELL>
__device__ __forceinline__ void doEll(const float* __restrict__ rep,
                                      float* __restrict__ sh,
                                      int b, int i0, int j0,
                                      int tau, int ty, int tid, bool mirror,
                                      float2* __restrict__ out) {
  using namespace cfg;
  constexpr int M = 2 * ELL + 1;

  // ---- raw coalesced copy of B tile: sh[(jl*32+tau)*2M + 2m + c]
  {
    const float4* src = reinterpret_cast<const float4*>(
        rep + (size_t)(b * kN + j0) * (kT * M * 2));
    float4* dst = reinterpret_cast<float4*>(sh);
#pragma unroll
    for (int k = 0; k < M; ++k)            // exactly M iterations of 256 thr
      dst[tid + k * NT] = src[tid + k * NT];
  }

  // ---- A with flip+sign folded, KI i-rows, this thread's tau
  float ar[KI][M], ai[KI][M];
#pragma unroll
  for (int ki = 0; ki < KI; ++ki) {
    int i = i0 + ty + ki * TY;
    const float2* ab = reinterpret_cast<const float2*>(rep) +
                       (size_t)((b * kN + i) * kT + tau) * M;
#pragma unroll
    for (int m = 0; m < M; ++m) {
      float2 v = __ldg(&ab[M - 1 - m]);
      float s = ((m + ELL) & 1) ? -1.0f : 1.0f;
      ar[ki][m] = s * v.x;
      ai[ki][m] = s * v.y;
    }
  }
  __syncthreads();

#pragma unroll 4
  for (int jl = 0; jl < JT; ++jl) {
    const float2* bp =
        reinterpret_cast<const float2*>(sh) + (jl * kT + tau) * M;
    float a1[KI], a2[KI], ci[KI];
#pragma unroll
    for (int ki = 0; ki < KI; ++ki) { a1[ki] = 0.f; a2[ki] = 0.f; ci[ki] = 0.f; }
#pragma unroll
    for (int m = 0; m < M; ++m) {
      float2 bv = bp[m];                   // conflict-free LDS.64
#pragma unroll
      for (int ki = 0; ki < KI; ++ki) {
        a1[ki] = fmaf(ar[ki][m], bv.x, a1[ki]);
        a2[ki] = fmaf(ai[ki][m], bv.y, a2[ki]);
        ci[ki] = fmaf(ar[ki][m], bv.y, ci[ki]);
        ci[ki] = fmaf(ai[ki][m], bv.x, ci[ki]);
      }
    }
    int j = j0 + jl;
#pragma unroll
    for (int ki = 0; ki < KI; ++ki) {
      int i = i0 + ty + ki * TY;
      float2 val = make_float2(a1[ki] - a2[ki], ci[ki]);
      size_t o1 = ((size_t)((b * kN + i) * kN + j)) * 128 + ELL * kT + tau;
      __stcs(&out[o1], val);               // streaming store
      if (mirror) {
        size_t o2 = ((size_t)((b * kN + j) * kN + i)) * 128 + ELL * kT + tau;
        __stcs(&out[o2], val);
      }
    }
  }
  __syncthreads();  // smem reused by the next ell
}

__global__ void __launch_bounds__(cfg::NT, 4)
dotmat_kernel(const float* __restrict__ r0, const float* __restrict__ r1,
              const float* __restrict__ r2, const float* __restrict__ r3,
              float2* __restrict__ out) {
  using namespace cfg;
  __shared__ float sh[SHF];
  const int tau = threadIdx.x;
  const int ty  = threadIdx.y;
  const int tid = ty * 32 + tau;
  const int b   = blockIdx.y;

  // decode upper-triangular pair index p -> (bi, bj), bi <= bj
  // T(r) = r*(33-r)/2 is the first pair index of row r
  const int p = blockIdx.x;
  int bi = (int)((33.0f - sqrtf(1089.0f - 8.0f * (float)p)) * 0.5f);
  while ((bi + 1) * (33 - (bi + 1)) / 2 <= p) ++bi;
  while (bi * (33 - bi) / 2 > p) --bi;
  const int bj = bi + (p - bi * (33 - bi) / 2);

  const int i0 = bi * IT;
  const int j0 = bj * JT;
  const bool mirror = (bi != bj);

  doEll<0>(r0, sh, b, i0, j0, tau, ty, tid, mirror, out);
  doEll<1>(r1, sh, b, i0, j0, tau, ty, tid, mirror, out);
  doEll<2>(r2, sh, b, i0, j0, tau, ty, tid, mirror, out);
  doEll<3>(r3, sh, b, i0, j0, tau, ty, tid, mirror, out);
}

extern "C" void kernel_launch(void* const* d_in, const int* in_sizes, int n_in,
                              void* d_out, int out_size) {
  (void)in_sizes; (void)n_in; (void)out_size;
  dim3 grid(cfg::NPAIRS, 2);     // 136 tile pairs x 2 batches
  dim3 block(32, cfg::TY);       // 256 threads
  dotmat_kernel<<<grid, block>>>(
      (const float*)d_in[0], (const float*)d_in[1],
      (const float*)d_in[2], (const float*)d_in[3],
      (float2*)d_out);
}